// round 5
// baseline (speedup 1.0000x reference)
#include <cuda_runtime.h>
#include <cstdint>
#include <math.h>

#define NTOK 4096
#define HDIM 768
#define FDIM 3072
#define ENUM 6
#define NSLOT (NTOK * 2)

// double-buffered stage: A 128x36 u32 + B 32x136 u32
#define A_U32 (128 * 36)
#define B_U32 (32 * 136)
#define STG_U32 (A_U32 + B_U32)          // 8960
#define SMEM_REQ (2 * STG_U32 * 4)       // 71680 bytes

// ---------------- device scratch (no allocations allowed) ----------------
__device__ int   g_counts[ENUM];
__device__ int   g_offsets[ENUM + 1];
__device__ int   g_fill[ENUM];
__device__ int   g_tk_idx[NSLOT];
__device__ float g_tk_w[NSLOT];
__device__ int   g_slot_tok[NSLOT];
__device__ float g_slot_w[NSLOT];
__device__ float g_xr[(size_t)NTOK * HDIM];          // tf32-rounded x
__device__ float g_hmid[(size_t)NSLOT * FDIM];       // tf32-rounded mid acts
__device__ float g_w1r[(size_t)ENUM * HDIM * FDIM];  // tf32-rounded w1 [E][K][N]
__device__ float g_w2r[(size_t)ENUM * FDIM * HDIM];  // tf32-rounded w2 [E][K][N]

// ---------------- helpers ----------------
__device__ __forceinline__ float f2tf(float x) {
    uint32_t r;
    asm("cvt.rna.tf32.f32 %0, %1;" : "=r"(r) : "f"(x));
    return __uint_as_float(r);
}
__device__ __forceinline__ float gelu_exact(float x) {
    return 0.5f * x * (1.0f + erff(x * 0.7071067811865476f));
}
__device__ __forceinline__ void mma_tf32(float* c, const uint32_t* a, const uint32_t* b) {
    asm volatile(
        "mma.sync.aligned.m16n8k8.row.col.f32.tf32.tf32.f32 "
        "{%0,%1,%2,%3}, {%4,%5,%6,%7}, {%8,%9}, {%0,%1,%2,%3};\n"
        : "+f"(c[0]), "+f"(c[1]), "+f"(c[2]), "+f"(c[3])
        : "r"(a[0]), "r"(a[1]), "r"(a[2]), "r"(a[3]), "r"(b[0]), "r"(b[1]));
}

// ---------------- kernel: zero output + routing counters ----------------
__global__ void zero_kernel(float* __restrict__ out) {
    int i = blockIdx.x * blockDim.x + threadIdx.x;
    if (i < NTOK * HDIM) out[i] = 0.0f;
    if (i < ENUM) { g_counts[i] = 0; g_fill[i] = 0; }
}

// ---------------- tf32 pre-rounding into DEVICE-SYMBOL scratch ----------------
// NOTE: the destination globals are referenced from device code (NOT passed from
// host) — passing a __device__ symbol as a host-side kernel arg silently writes
// to the host shadow on GB300 (ATS) and was the R3/R4 correctness bug.
__global__ void round_x_k(const float* __restrict__ src) {
    int i = blockIdx.x * blockDim.x + threadIdx.x;
    if (i < NTOK * HDIM) g_xr[i] = f2tf(src[i]);
}
__global__ void round_w1_k(const float* __restrict__ src) {
    size_t i = (size_t)blockIdx.x * blockDim.x + threadIdx.x;
    if (i < (size_t)ENUM * HDIM * FDIM) g_w1r[i] = f2tf(src[i]);
}
__global__ void round_w2_k(const float* __restrict__ src) {
    size_t i = (size_t)blockIdx.x * blockDim.x + threadIdx.x;
    if (i < (size_t)ENUM * FDIM * HDIM) g_w2r[i] = f2tf(src[i]);
}

// ---------------- gate: scores + top-2 + softmax + counts ----------------
__global__ void gate_kernel(const float* __restrict__ x,
                            const float* __restrict__ gw,
                            const float* __restrict__ gb) {
    const int warp = threadIdx.x >> 5;
    const int lane = threadIdx.x & 31;
    const int tok = blockIdx.x * 8 + warp;
    if (tok >= NTOK) return;

    float acc[ENUM];
#pragma unroll
    for (int e = 0; e < ENUM; ++e) acc[e] = 0.0f;

    const float* xr = x + (size_t)tok * HDIM;
    for (int h = lane; h < HDIM; h += 32) {
        float xv = xr[h];
#pragma unroll
        for (int e = 0; e < ENUM; ++e) acc[e] += xv * gw[h * ENUM + e];
    }
#pragma unroll
    for (int e = 0; e < ENUM; ++e) {
#pragma unroll
        for (int off = 16; off > 0; off >>= 1)
            acc[e] += __shfl_xor_sync(0xffffffffu, acc[e], off);
    }
    if (lane == 0) {
        float best = -1e30f, sec = -1e30f;
        int bi = 0, si = 0;
#pragma unroll
        for (int e = 0; e < ENUM; ++e) {
            float s = acc[e] + gb[e];
            if (s > best) { sec = best; si = bi; best = s; bi = e; }
            else if (s > sec) { sec = s; si = e; }
        }
        float r = expf(sec - best);
        float inv = 1.0f / (1.0f + r);
        g_tk_idx[tok * 2]     = bi;
        g_tk_idx[tok * 2 + 1] = si;
        g_tk_w[tok * 2]       = inv;
        g_tk_w[tok * 2 + 1]   = r * inv;
        atomicAdd(&g_counts[bi], 1);
        atomicAdd(&g_counts[si], 1);
    }
}

__global__ void scan_kernel() {
    if (threadIdx.x == 0 && blockIdx.x == 0) {
        int o = 0;
#pragma unroll
        for (int e = 0; e < ENUM; ++e) { g_offsets[e] = o; o += g_counts[e]; }
        g_offsets[ENUM] = o;
    }
}

__global__ void scatter_kernel() {
    int n = blockIdx.x * blockDim.x + threadIdx.x;
    if (n >= NTOK) return;
#pragma unroll
    for (int k = 0; k < 2; ++k) {
        int e = g_tk_idx[n * 2 + k];
        int pos = g_offsets[e] + atomicAdd(&g_fill[e], 1);
        g_slot_tok[pos] = n;
        g_slot_w[pos]   = g_tk_w[n * 2 + k];
    }
}

// ---------------- grouped GEMM (tf32 mma.sync), double-buffered smem ----------
// PHASE 1: hmid = round(gelu(gather(xr) @ w1r + b1))
// PHASE 2: out += slot_w * (hmid @ w2r + b2)   (atomicAdd combine)
template <int PHASE>
__global__ void __launch_bounds__(256, 1) moe_gemm(const float* __restrict__ bias,
                                                   float* __restrict__ out) {
    constexpr int KDIM = (PHASE == 1) ? HDIM : FDIM;
    constexpr int LDB  = (PHASE == 1) ? FDIM : HDIM;
    constexpr int KT   = KDIM / 32;

    const int e    = blockIdx.z;
    const int base = g_offsets[e];
    const int cnt  = g_offsets[e + 1] - base;
    const int m0   = blockIdx.y * 128;
    if (m0 >= cnt) return;
    const int n0 = blockIdx.x * 128;

    const float* Bm = ((PHASE == 1) ? g_w1r : g_w2r) + (size_t)e * KDIM * LDB;

    extern __shared__ uint32_t Su[];   // [2][STG_U32]

    const int tid = threadIdx.x;
    const int ar = tid >> 3;          // 0..31  (A: 32 rows / pass)
    const int ac = (tid & 7) << 2;    // col*4
    const int br = tid >> 5;          // 0..7   (B: 8 rows / pass)
    const int bc = (tid & 31) << 2;

    // resolve A row pointers once (gathered for PHASE 1, contiguous for PHASE 2)
    const float* arow[4];
#pragma unroll
    for (int p = 0; p < 4; ++p) {
        int r = m0 + p * 32 + ar;
        if (r < cnt) {
            if (PHASE == 1) arow[p] = g_xr + (size_t)g_slot_tok[base + r] * HDIM;
            else            arow[p] = g_hmid + (size_t)(base + r) * FDIM;
        } else arow[p] = nullptr;
    }

    float4 aReg[4], bReg[4];
    auto load_tile = [&](int k0) {
#pragma unroll
        for (int p = 0; p < 4; ++p) {
            aReg[p] = arow[p] ? *(const float4*)(arow[p] + k0 + ac)
                              : make_float4(0.f, 0.f, 0.f, 0.f);
            bReg[p] = *(const float4*)(Bm + (size_t)(k0 + p * 8 + br) * LDB + n0 + bc);
        }
    };
    auto store_tile = [&](int b) {
        uint32_t* As = Su + b * STG_U32;
        uint32_t* Bs = As + A_U32;
#pragma unroll
        for (int p = 0; p < 4; ++p) {
            *(float4*)&As[(p * 32 + ar) * 36 + ac] = aReg[p];
            *(float4*)&Bs[(p * 8 + br) * 136 + bc] = bReg[p];
        }
    };

    load_tile(0);
    store_tile(0);
    __syncthreads();

    const int warp = tid >> 5, lane = tid & 31;
    const int wm = (warp >> 2) * 64;
    const int wn = (warp & 3) * 32;
    const int g = lane >> 2, t = lane & 3;

    float acc[4][4][4];
#pragma unroll
    for (int mf = 0; mf < 4; ++mf)
#pragma unroll
        for (int nf = 0; nf < 4; ++nf)
#pragma unroll
            for (int c = 0; c < 4; ++c) acc[mf][nf][c] = 0.0f;

    for (int kt = 0; kt < KT; ++kt) {
        if (kt + 1 < KT) load_tile((kt + 1) * 32);  // prefetch next tile into regs

        const uint32_t* au = Su + (kt & 1) * STG_U32;
        const uint32_t* bu = au + A_U32;
#pragma unroll
        for (int s = 0; s < 4; ++s) {
            uint32_t af[4][4];
#pragma unroll
            for (int mf = 0; mf < 4; ++mf) {
                const uint32_t* Ap = &au[(wm + mf * 16 + g) * 36 + s * 8 + t];
                af[mf][0] = Ap[0];
                af[mf][1] = Ap[8 * 36];
                af[mf][2] = Ap[4];
                af[mf][3] = Ap[8 * 36 + 4];
            }
            uint32_t bf[4][2];
#pragma unroll
            for (int nf = 0; nf < 4; ++nf) {
                bf[nf][0] = bu[(s * 8 + t) * 136 + wn + nf * 8 + g];
                bf[nf][1] = bu[(s * 8 + t + 4) * 136 + wn + nf * 8 + g];
            }
#pragma unroll
            for (int mf = 0; mf < 4; ++mf)
#pragma unroll
                for (int nf = 0; nf < 4; ++nf)
                    mma_tf32(acc[mf][nf], af[mf], bf[nf]);
        }
        if (kt + 1 < KT) {
            store_tile((kt + 1) & 1);   // other buffer, protected by this sync
            __syncthreads();
        }
    }

    // -------- epilogue --------
    const float* bv = bias + (size_t)e * LDB;
#pragma unroll
    for (int mf = 0; mf < 4; ++mf) {
        int rl = wm + mf * 16 + g;
#pragma unroll
        for (int nf = 0; nf < 4; ++nf) {
            int col = n0 + wn + nf * 8 + 2 * t;
            float bb0 = bv[col], bb1 = bv[col + 1];
#pragma unroll
            for (int half = 0; half < 2; ++half) {
                int mrow = m0 + rl + half * 8;
                if (mrow >= cnt) continue;
                float v0 = acc[mf][nf][half * 2 + 0] + bb0;
                float v1 = acc[mf][nf][half * 2 + 1] + bb1;
                if (PHASE == 1) {
                    size_t o = (size_t)(base + mrow) * FDIM + col;
                    g_hmid[o]     = f2tf(gelu_exact(v0));
                    g_hmid[o + 1] = f2tf(gelu_exact(v1));
                } else {
                    int slot = base + mrow;
                    int tok = g_slot_tok[slot];
                    float w = g_slot_w[slot];
                    atomicAdd(&out[(size_t)tok * HDIM + col],     w * v0);
                    atomicAdd(&out[(size_t)tok * HDIM + col + 1], w * v1);
                }
            }
        }
    }
}

// ---------------- launch ----------------
extern "C" void kernel_launch(void* const* d_in, const int* in_sizes, int n_in,
                              void* d_out, int out_size) {
    const float* x  = (const float*)d_in[0];
    const float* gw = (const float*)d_in[1];
    const float* gb = (const float*)d_in[2];
    const float* w1 = (const float*)d_in[3];
    const float* b1 = (const float*)d_in[4];
    const float* w2 = (const float*)d_in[5];
    const float* b2 = (const float*)d_in[6];
    float* out = (float*)d_out;

    cudaFuncSetAttribute(moe_gemm<1>, cudaFuncAttributeMaxDynamicSharedMemorySize, SMEM_REQ);
    cudaFuncSetAttribute(moe_gemm<2>, cudaFuncAttributeMaxDynamicSharedMemorySize, SMEM_REQ);

    zero_kernel<<<(NTOK * HDIM + 255) / 256, 256>>>(out);
    gate_kernel<<<NTOK / 8, 256>>>(x, gw, gb);
    scan_kernel<<<1, 32>>>();
    scatter_kernel<<<(NTOK + 255) / 256, 256>>>();

    round_x_k<<<(NTOK * HDIM + 255) / 256, 256>>>(x);
    round_w1_k<<<(ENUM * HDIM * FDIM + 255) / 256, 256>>>(w1);
    round_w2_k<<<(ENUM * FDIM * HDIM + 255) / 256, 256>>>(w2);

    moe_gemm<1><<<dim3(FDIM / 128, NSLOT / 128, ENUM), 256, SMEM_REQ>>>(b1, nullptr);
    moe_gemm<2><<<dim3(HDIM / 128, NSLOT / 128, ENUM), 256, SMEM_REQ>>>(b2, out);
}

// round 6
// speedup vs baseline: 1.1624x; 1.1624x over previous
#include <cuda_runtime.h>
#include <cstdint>
#include <math.h>

#define NTOK 4096
#define HDIM 768
#define FDIM 3072
#define ENUM 6
#define NSLOT (NTOK * 2)

// double-buffered stage: A 128x36 u32 + B 32x136 u32
#define A_U32 (128 * 36)
#define B_U32 (32 * 136)
#define STG_U32 (A_U32 + B_U32)          // 8960
#define SMEM_REQ (2 * STG_U32 * 4)       // 71680 bytes -> 2 CTAs/SM (143KB)

// ---------------- device scratch (no allocations allowed) ----------------
__device__ int   g_counts[ENUM];
__device__ int   g_offsets[ENUM + 1];
__device__ int   g_fill[ENUM];
__device__ int   g_tk_idx[NSLOT];
__device__ float g_tk_w[NSLOT];
__device__ int   g_slot_tok[NSLOT];
__device__ float g_slot_w[NSLOT];
__device__ float g_xr[(size_t)NTOK * HDIM];          // tf32-rounded x
__device__ float g_hmid[(size_t)NSLOT * FDIM];       // tf32-rounded mid acts
__device__ float g_w1r[(size_t)ENUM * HDIM * FDIM];  // tf32-rounded w1 [E][K][N]
__device__ float g_w2r[(size_t)ENUM * FDIM * HDIM];  // tf32-rounded w2 [E][K][N]

// ---------------- helpers ----------------
__device__ __forceinline__ float f2tf(float x) {
    uint32_t r;
    asm("cvt.rna.tf32.f32 %0, %1;" : "=r"(r) : "f"(x));
    return __uint_as_float(r);
}
__device__ __forceinline__ float gelu_exact(float x) {
    return 0.5f * x * (1.0f + erff(x * 0.7071067811865476f));
}
__device__ __forceinline__ uint32_t smem_u32(const void* p) {
    uint32_t a;
    asm("{ .reg .u64 t; cvta.to.shared.u64 t, %1; cvt.u32.u64 %0, t; }" : "=r"(a) : "l"(p));
    return a;
}
__device__ __forceinline__ void cp16(uint32_t dst, const void* src, bool pred) {
    int sz = pred ? 16 : 0;   // src-size 0 => zero-fill, no gmem access
    asm volatile("cp.async.cg.shared.global [%0], [%1], 16, %2;"
                 :: "r"(dst), "l"(src), "r"(sz) : "memory");
}
#define CP_COMMIT() asm volatile("cp.async.commit_group;" ::: "memory")
#define CP_WAIT(n)  asm volatile("cp.async.wait_group %0;" :: "n"(n) : "memory")

__device__ __forceinline__ void mma_tf32(float* c, const uint32_t* a, const uint32_t* b) {
    asm volatile(
        "mma.sync.aligned.m16n8k8.row.col.f32.tf32.tf32.f32 "
        "{%0,%1,%2,%3}, {%4,%5,%6,%7}, {%8,%9}, {%0,%1,%2,%3};\n"
        : "+f"(c[0]), "+f"(c[1]), "+f"(c[2]), "+f"(c[3])
        : "r"(a[0]), "r"(a[1]), "r"(a[2]), "r"(a[3]), "r"(b[0]), "r"(b[1]));
}

// ---------------- kernel: zero output + routing counters ----------------
__global__ void zero_kernel(float* __restrict__ out) {
    int i = blockIdx.x * blockDim.x + threadIdx.x;
    if (i < NTOK * HDIM) out[i] = 0.0f;
    if (i < ENUM) { g_counts[i] = 0; g_fill[i] = 0; }
}

// ---------------- tf32 pre-rounding into DEVICE-SYMBOL scratch ----------------
// (destinations referenced from device code; host-passed __device__ symbols
//  silently hit the host shadow via ATS on GB300 — the R3/R4 bug)
__global__ void round_x_k(const float* __restrict__ src) {
    int i = blockIdx.x * blockDim.x + threadIdx.x;
    if (i < NTOK * HDIM) g_xr[i] = f2tf(src[i]);
}
__global__ void round_w1_k(const float* __restrict__ src) {
    size_t i = (size_t)blockIdx.x * blockDim.x + threadIdx.x;
    if (i < (size_t)ENUM * HDIM * FDIM) g_w1r[i] = f2tf(src[i]);
}
__global__ void round_w2_k(const float* __restrict__ src) {
    size_t i = (size_t)blockIdx.x * blockDim.x + threadIdx.x;
    if (i < (size_t)ENUM * FDIM * HDIM) g_w2r[i] = f2tf(src[i]);
}

// ---------------- gate: scores + top-2 + softmax + counts ----------------
__global__ void gate_kernel(const float* __restrict__ x,
                            const float* __restrict__ gw,
                            const float* __restrict__ gb) {
    const int warp = threadIdx.x >> 5;
    const int lane = threadIdx.x & 31;
    const int tok = blockIdx.x * 8 + warp;
    if (tok >= NTOK) return;

    float acc[ENUM];
#pragma unroll
    for (int e = 0; e < ENUM; ++e) acc[e] = 0.0f;

    const float* xr = x + (size_t)tok * HDIM;
    for (int h = lane; h < HDIM; h += 32) {
        float xv = xr[h];
#pragma unroll
        for (int e = 0; e < ENUM; ++e) acc[e] += xv * gw[h * ENUM + e];
    }
#pragma unroll
    for (int e = 0; e < ENUM; ++e) {
#pragma unroll
        for (int off = 16; off > 0; off >>= 1)
            acc[e] += __shfl_xor_sync(0xffffffffu, acc[e], off);
    }
    if (lane == 0) {
        float best = -1e30f, sec = -1e30f;
        int bi = 0, si = 0;
#pragma unroll
        for (int e = 0; e < ENUM; ++e) {
            float s = acc[e] + gb[e];
            if (s > best) { sec = best; si = bi; best = s; bi = e; }
            else if (s > sec) { sec = s; si = e; }
        }
        float r = expf(sec - best);
        float inv = 1.0f / (1.0f + r);
        g_tk_idx[tok * 2]     = bi;
        g_tk_idx[tok * 2 + 1] = si;
        g_tk_w[tok * 2]       = inv;
        g_tk_w[tok * 2 + 1]   = r * inv;
        atomicAdd(&g_counts[bi], 1);
        atomicAdd(&g_counts[si], 1);
    }
}

__global__ void scan_kernel() {
    if (threadIdx.x == 0 && blockIdx.x == 0) {
        int o = 0;
#pragma unroll
        for (int e = 0; e < ENUM; ++e) { g_offsets[e] = o; o += g_counts[e]; }
        g_offsets[ENUM] = o;
    }
}

__global__ void scatter_kernel() {
    int n = blockIdx.x * blockDim.x + threadIdx.x;
    if (n >= NTOK) return;
#pragma unroll
    for (int k = 0; k < 2; ++k) {
        int e = g_tk_idx[n * 2 + k];
        int pos = g_offsets[e] + atomicAdd(&g_fill[e], 1);
        g_slot_tok[pos] = n;
        g_slot_w[pos]   = g_tk_w[n * 2 + k];
    }
}

// ---------------- grouped GEMM (tf32 mma.sync), cp.async 2-stage, 2 CTAs/SM ----
// PHASE 1: hmid = round(gelu(gather(xr) @ w1r + b1))
// PHASE 2: out += slot_w * (hmid @ w2r + b2)   (atomicAdd combine)
template <int PHASE>
__global__ void __launch_bounds__(256, 2) moe_gemm(const float* __restrict__ bias,
                                                   float* __restrict__ out) {
    constexpr int KDIM = (PHASE == 1) ? HDIM : FDIM;
    constexpr int LDB  = (PHASE == 1) ? FDIM : HDIM;
    constexpr int KT   = KDIM / 32;

    const int e    = blockIdx.z;
    const int base = g_offsets[e];
    const int cnt  = g_offsets[e + 1] - base;
    const int m0   = blockIdx.y * 128;
    if (m0 >= cnt) return;
    const int n0 = blockIdx.x * 128;

    const float* Bm = ((PHASE == 1) ? g_w1r : g_w2r) + (size_t)e * KDIM * LDB;

    extern __shared__ uint32_t Su[];   // [2][STG_U32]
    const uint32_t sb = smem_u32(Su);

    const int tid = threadIdx.x;
    const int ar = tid >> 3;          // 0..31  (A: 32 rows / pass)
    const int ac = (tid & 7) << 2;    // col*4
    const int br = tid >> 5;          // 0..7   (B: 8 rows / pass)
    const int bc = (tid & 31) << 2;

    // resolve A row pointers once (gathered for PHASE 1, contiguous for PHASE 2)
    const float* arow[4];
#pragma unroll
    for (int p = 0; p < 4; ++p) {
        int r = m0 + p * 32 + ar;
        if (r < cnt) {
            if (PHASE == 1) arow[p] = g_xr + (size_t)g_slot_tok[base + r] * HDIM;
            else            arow[p] = g_hmid + (size_t)(base + r) * FDIM;
        } else arow[p] = nullptr;
    }

    auto issue = [&](int b, int k0) {
        uint32_t a_s = sb + (b * STG_U32) * 4;
        uint32_t b_s = a_s + A_U32 * 4;
#pragma unroll
        for (int p = 0; p < 4; ++p) {
            cp16(a_s + ((p * 32 + ar) * 36 + ac) * 4,
                 arow[p] ? (arow[p] + k0 + ac) : (const float*)Bm, arow[p] != nullptr);
            cp16(b_s + ((p * 8 + br) * 136 + bc) * 4,
                 Bm + (size_t)(k0 + p * 8 + br) * LDB + n0 + bc, true);
        }
    };

    issue(0, 0);
    CP_COMMIT();

    const int warp = tid >> 5, lane = tid & 31;
    const int wm = (warp >> 2) * 64;
    const int wn = (warp & 3) * 32;
    const int g = lane >> 2, t = lane & 3;

    float acc[4][4][4];
#pragma unroll
    for (int mf = 0; mf < 4; ++mf)
#pragma unroll
        for (int nf = 0; nf < 4; ++nf)
#pragma unroll
            for (int c = 0; c < 4; ++c) acc[mf][nf][c] = 0.0f;

    for (int kt = 0; kt < KT; ++kt) {
        if (kt + 1 < KT) {
            issue((kt + 1) & 1, (kt + 1) * 32);
            CP_COMMIT();
            CP_WAIT(1);               // current stage (committed last iter) arrived
        } else {
            CP_WAIT(0);
        }
        __syncthreads();

        const uint32_t* au = Su + (kt & 1) * STG_U32;
        const uint32_t* bu = au + A_U32;
#pragma unroll
        for (int s = 0; s < 4; ++s) {
            uint32_t af[4][4];
#pragma unroll
            for (int mf = 0; mf < 4; ++mf) {
                const uint32_t* Ap = &au[(wm + mf * 16 + g) * 36 + s * 8 + t];
                af[mf][0] = Ap[0];
                af[mf][1] = Ap[8 * 36];
                af[mf][2] = Ap[4];
                af[mf][3] = Ap[8 * 36 + 4];
            }
            uint32_t bf[4][2];
#pragma unroll
            for (int nf = 0; nf < 4; ++nf) {
                bf[nf][0] = bu[(s * 8 + t) * 136 + wn + nf * 8 + g];
                bf[nf][1] = bu[(s * 8 + t + 4) * 136 + wn + nf * 8 + g];
            }
#pragma unroll
            for (int mf = 0; mf < 4; ++mf)
#pragma unroll
                for (int nf = 0; nf < 4; ++nf)
                    mma_tf32(acc[mf][nf], af[mf], bf[nf]);
        }
        __syncthreads();   // stage kt&1 fully consumed before next iter's issue overwrites it
    }

    // -------- epilogue --------
    const float* bv = bias + (size_t)e * LDB;
#pragma unroll
    for (int mf = 0; mf < 4; ++mf) {
        int rl = wm + mf * 16 + g;
#pragma unroll
        for (int nf = 0; nf < 4; ++nf) {
            int col = n0 + wn + nf * 8 + 2 * t;
            float bb0 = bv[col], bb1 = bv[col + 1];
#pragma unroll
            for (int half = 0; half < 2; ++half) {
                int mrow = m0 + rl + half * 8;
                if (mrow >= cnt) continue;
                float v0 = acc[mf][nf][half * 2 + 0] + bb0;
                float v1 = acc[mf][nf][half * 2 + 1] + bb1;
                if (PHASE == 1) {
                    size_t o = (size_t)(base + mrow) * FDIM + col;
                    g_hmid[o]     = f2tf(gelu_exact(v0));
                    g_hmid[o + 1] = f2tf(gelu_exact(v1));
                } else {
                    int slot = base + mrow;
                    int tok = g_slot_tok[slot];
                    float w = g_slot_w[slot];
                    atomicAdd(&out[(size_t)tok * HDIM + col],     w * v0);
                    atomicAdd(&out[(size_t)tok * HDIM + col + 1], w * v1);
                }
            }
        }
    }
}

// ---------------- launch ----------------
extern "C" void kernel_launch(void* const* d_in, const int* in_sizes, int n_in,
                              void* d_out, int out_size) {
    const float* x  = (const float*)d_in[0];
    const float* gw = (const float*)d_in[1];
    const float* gb = (const float*)d_in[2];
    const float* w1 = (const float*)d_in[3];
    const float* b1 = (const float*)d_in[4];
    const float* w2 = (const float*)d_in[5];
    const float* b2 = (const float*)d_in[6];
    float* out = (float*)d_out;

    cudaFuncSetAttribute(moe_gemm<1>, cudaFuncAttributeMaxDynamicSharedMemorySize, SMEM_REQ);
    cudaFuncSetAttribute(moe_gemm<2>, cudaFuncAttributeMaxDynamicSharedMemorySize, SMEM_REQ);

    zero_kernel<<<(NTOK * HDIM + 255) / 256, 256>>>(out);
    gate_kernel<<<NTOK / 8, 256>>>(x, gw, gb);
    scan_kernel<<<1, 32>>>();
    scatter_kernel<<<(NTOK + 255) / 256, 256>>>();

    round_x_k<<<(NTOK * HDIM + 255) / 256, 256>>>(x);
    round_w1_k<<<(ENUM * HDIM * FDIM + 255) / 256, 256>>>(w1);
    round_w2_k<<<(ENUM * FDIM * HDIM + 255) / 256, 256>>>(w2);

    moe_gemm<1><<<dim3(FDIM / 128, NSLOT / 128, ENUM), 256, SMEM_REQ>>>(b1, nullptr);
    moe_gemm<2><<<dim3(HDIM / 128, NSLOT / 128, ENUM), 256, SMEM_REQ>>>(b2, out);
}

// round 7
// speedup vs baseline: 1.1819x; 1.0168x over previous
#include <cuda_runtime.h>
#include <cstdint>
#include <math.h>

#define NTOK 4096
#define HDIM 768
#define FDIM 3072
#define ENUM 6
#define NSLOT (NTOK * 2)

// 3-stage pipeline: stage = A 128x36 u32 + B 32x136 u32
#define A_U32 (128 * 36)
#define B_U32 (32 * 136)
#define STG_U32 (A_U32 + B_U32)          // 8960 u32 = 35840 B
#define N_STAGES 3
#define SMEM_REQ (N_STAGES * STG_U32 * 4) // 107520 B -> still 2 CTAs/SM (215KB)

// ---------------- device scratch (no allocations allowed) ----------------
__device__ int   g_counts[ENUM];
__device__ int   g_offsets[ENUM + 1];
__device__ int   g_fill[ENUM];
__device__ int   g_tk_idx[NSLOT];
__device__ float g_tk_w[NSLOT];
__device__ int   g_slot_tok[NSLOT];
__device__ float g_slot_w[NSLOT];
__device__ float g_xr[(size_t)NTOK * HDIM];          // tf32-rounded x
__device__ float g_hmid[(size_t)NSLOT * FDIM];       // tf32-rounded mid acts
__device__ float g_w1r[(size_t)ENUM * HDIM * FDIM];  // tf32-rounded w1 [E][K][N]
__device__ float g_w2r[(size_t)ENUM * FDIM * HDIM];  // tf32-rounded w2 [E][K][N]

// ---------------- helpers ----------------
__device__ __forceinline__ float f2tf(float x) {
    uint32_t r;
    asm("cvt.rna.tf32.f32 %0, %1;" : "=r"(r) : "f"(x));
    return __uint_as_float(r);
}
__device__ __forceinline__ float gelu_exact(float x) {
    return 0.5f * x * (1.0f + erff(x * 0.7071067811865476f));
}
__device__ __forceinline__ uint32_t smem_u32(const void* p) {
    uint32_t a;
    asm("{ .reg .u64 t; cvta.to.shared.u64 t, %1; cvt.u32.u64 %0, t; }" : "=r"(a) : "l"(p));
    return a;
}
__device__ __forceinline__ void cp16(uint32_t dst, const void* src, bool pred) {
    int sz = pred ? 16 : 0;   // src-size 0 => zero-fill, no gmem access
    asm volatile("cp.async.cg.shared.global [%0], [%1], 16, %2;"
                 :: "r"(dst), "l"(src), "r"(sz) : "memory");
}
#define CP_COMMIT() asm volatile("cp.async.commit_group;" ::: "memory")
#define CP_WAIT(n)  asm volatile("cp.async.wait_group %0;" :: "n"(n) : "memory")

__device__ __forceinline__ void mma_tf32(float* c, const uint32_t* a, const uint32_t* b) {
    asm volatile(
        "mma.sync.aligned.m16n8k8.row.col.f32.tf32.tf32.f32 "
        "{%0,%1,%2,%3}, {%4,%5,%6,%7}, {%8,%9}, {%0,%1,%2,%3};\n"
        : "+f"(c[0]), "+f"(c[1]), "+f"(c[2]), "+f"(c[3])
        : "r"(a[0]), "r"(a[1]), "r"(a[2]), "r"(a[3]), "r"(b[0]), "r"(b[1]));
}

// ---------------- kernel: zero output + routing counters ----------------
__global__ void zero_kernel(float* __restrict__ out) {
    int i = blockIdx.x * blockDim.x + threadIdx.x;
    if (i < NTOK * HDIM) out[i] = 0.0f;
    if (i < ENUM) { g_counts[i] = 0; g_fill[i] = 0; }
}

// ---------------- tf32 pre-rounding into DEVICE-SYMBOL scratch ----------------
// (destinations referenced from device code; host-passed __device__ symbols
//  silently hit the host shadow via ATS on GB300 — the R3/R4 bug)
__global__ void round_x_k(const float* __restrict__ src) {
    int i = blockIdx.x * blockDim.x + threadIdx.x;
    if (i < NTOK * HDIM) g_xr[i] = f2tf(src[i]);
}
__global__ void round_w1_k(const float* __restrict__ src) {
    size_t i = (size_t)blockIdx.x * blockDim.x + threadIdx.x;
    if (i < (size_t)ENUM * HDIM * FDIM) g_w1r[i] = f2tf(src[i]);
}
__global__ void round_w2_k(const float* __restrict__ src) {
    size_t i = (size_t)blockIdx.x * blockDim.x + threadIdx.x;
    if (i < (size_t)ENUM * FDIM * HDIM) g_w2r[i] = f2tf(src[i]);
}

// ---------------- gate: scores + top-2 + softmax + counts ----------------
__global__ void gate_kernel(const float* __restrict__ x,
                            const float* __restrict__ gw,
                            const float* __restrict__ gb) {
    const int warp = threadIdx.x >> 5;
    const int lane = threadIdx.x & 31;
    const int tok = blockIdx.x * 8 + warp;
    if (tok >= NTOK) return;

    float acc[ENUM];
#pragma unroll
    for (int e = 0; e < ENUM; ++e) acc[e] = 0.0f;

    const float* xr = x + (size_t)tok * HDIM;
    for (int h = lane; h < HDIM; h += 32) {
        float xv = xr[h];
#pragma unroll
        for (int e = 0; e < ENUM; ++e) acc[e] += xv * gw[h * ENUM + e];
    }
#pragma unroll
    for (int e = 0; e < ENUM; ++e) {
#pragma unroll
        for (int off = 16; off > 0; off >>= 1)
            acc[e] += __shfl_xor_sync(0xffffffffu, acc[e], off);
    }
    if (lane == 0) {
        float best = -1e30f, sec = -1e30f;
        int bi = 0, si = 0;
#pragma unroll
        for (int e = 0; e < ENUM; ++e) {
            float s = acc[e] + gb[e];
            if (s > best) { sec = best; si = bi; best = s; bi = e; }
            else if (s > sec) { sec = s; si = e; }
        }
        float r = expf(sec - best);
        float inv = 1.0f / (1.0f + r);
        g_tk_idx[tok * 2]     = bi;
        g_tk_idx[tok * 2 + 1] = si;
        g_tk_w[tok * 2]       = inv;
        g_tk_w[tok * 2 + 1]   = r * inv;
        atomicAdd(&g_counts[bi], 1);
        atomicAdd(&g_counts[si], 1);
    }
}

__global__ void scan_kernel() {
    if (threadIdx.x == 0 && blockIdx.x == 0) {
        int o = 0;
#pragma unroll
        for (int e = 0; e < ENUM; ++e) { g_offsets[e] = o; o += g_counts[e]; }
        g_offsets[ENUM] = o;
    }
}

__global__ void scatter_kernel() {
    int n = blockIdx.x * blockDim.x + threadIdx.x;
    if (n >= NTOK) return;
#pragma unroll
    for (int k = 0; k < 2; ++k) {
        int e = g_tk_idx[n * 2 + k];
        int pos = g_offsets[e] + atomicAdd(&g_fill[e], 1);
        g_slot_tok[pos] = n;
        g_slot_w[pos]   = g_tk_w[n * 2 + k];
    }
}

// ---------------- grouped GEMM (tf32 mma.sync), 3-stage cp.async, 2 CTAs/SM ----
// PHASE 1 (KSPLIT=1): hmid = round(gelu(gather(xr) @ w1r + b1))
// PHASE 2 (KSPLIT=4): out += slot_w * (hmid @ w2r [+ b2 if ks==0]) via atomicAdd
template <int PHASE, int KSPLIT>
__global__ void __launch_bounds__(256, 2) moe_gemm(const float* __restrict__ bias,
                                                   float* __restrict__ out) {
    constexpr int KTOT = (PHASE == 1) ? HDIM : FDIM;
    constexpr int KDIM = KTOT / KSPLIT;
    constexpr int LDB  = (PHASE == 1) ? FDIM : HDIM;
    constexpr int KT   = KDIM / 32;

    const int e    = blockIdx.z / KSPLIT;
    const int ks   = blockIdx.z % KSPLIT;
    const int kb   = ks * KDIM;
    const int base = g_offsets[e];
    const int cnt  = g_offsets[e + 1] - base;
    const int m0   = blockIdx.y * 128;
    if (m0 >= cnt) return;
    const int n0 = blockIdx.x * 128;

    const float* Bm = ((PHASE == 1) ? g_w1r : g_w2r) + (size_t)e * KTOT * LDB;

    extern __shared__ uint32_t Su[];   // [N_STAGES][STG_U32]
    const uint32_t sb = smem_u32(Su);

    const int tid = threadIdx.x;
    const int ar = tid >> 3;          // 0..31  (A: 32 rows / pass)
    const int ac = (tid & 7) << 2;    // col*4
    const int br = tid >> 5;          // 0..7   (B: 8 rows / pass)
    const int bc = (tid & 31) << 2;

    // resolve A row pointers once (gathered for PHASE 1, contiguous for PHASE 2)
    const float* arow[4];
#pragma unroll
    for (int p = 0; p < 4; ++p) {
        int r = m0 + p * 32 + ar;
        if (r < cnt) {
            if (PHASE == 1) arow[p] = g_xr + (size_t)g_slot_tok[base + r] * HDIM + kb;
            else            arow[p] = g_hmid + (size_t)(base + r) * FDIM + kb;
        } else arow[p] = nullptr;
    }

    auto issue = [&](int b, int k0) {
        uint32_t a_s = sb + (b * STG_U32) * 4;
        uint32_t b_s = a_s + A_U32 * 4;
#pragma unroll
        for (int p = 0; p < 4; ++p) {
            cp16(a_s + ((p * 32 + ar) * 36 + ac) * 4,
                 arow[p] ? (arow[p] + k0 + ac) : (const float*)Bm, arow[p] != nullptr);
            cp16(b_s + ((p * 8 + br) * 136 + bc) * 4,
                 Bm + (size_t)(kb + k0 + p * 8 + br) * LDB + n0 + bc, true);
        }
    };

    issue(0, 0);  CP_COMMIT();
    issue(1, 32); CP_COMMIT();

    const int warp = tid >> 5, lane = tid & 31;
    const int wm = (warp >> 2) * 64;
    const int wn = (warp & 3) * 32;
    const int g = lane >> 2, t = lane & 3;

    float acc[4][4][4];
#pragma unroll
    for (int mf = 0; mf < 4; ++mf)
#pragma unroll
        for (int nf = 0; nf < 4; ++nf)
#pragma unroll
            for (int c = 0; c < 4; ++c) acc[mf][nf][c] = 0.0f;

    int st = 0;                       // stage of tile kt (mod N_STAGES)
    for (int kt = 0; kt < KT; ++kt) {
        CP_WAIT(1);                   // oldest outstanding group (stage kt) done
        __syncthreads();              // + all warps finished computing tile kt-1
        if (kt + 2 < KT) {
            int s2 = st + 2; if (s2 >= N_STAGES) s2 -= N_STAGES;
            issue(s2, (kt + 2) * 32); // overwrites stage consumed at iter kt-1: safe
            CP_COMMIT();
        }

        const uint32_t* au = Su + st * STG_U32;
        const uint32_t* bu = au + A_U32;
#pragma unroll
        for (int s = 0; s < 4; ++s) {
            uint32_t af[4][4];
#pragma unroll
            for (int mf = 0; mf < 4; ++mf) {
                const uint32_t* Ap = &au[(wm + mf * 16 + g) * 36 + s * 8 + t];
                af[mf][0] = Ap[0];
                af[mf][1] = Ap[8 * 36];
                af[mf][2] = Ap[4];
                af[mf][3] = Ap[8 * 36 + 4];
            }
            uint32_t bf[4][2];
#pragma unroll
            for (int nf = 0; nf < 4; ++nf) {
                bf[nf][0] = bu[(s * 8 + t) * 136 + wn + nf * 8 + g];
                bf[nf][1] = bu[(s * 8 + t + 4) * 136 + wn + nf * 8 + g];
            }
#pragma unroll
            for (int mf = 0; mf < 4; ++mf)
#pragma unroll
                for (int nf = 0; nf < 4; ++nf)
                    mma_tf32(acc[mf][nf], af[mf], bf[nf]);
        }
        if (++st == N_STAGES) st = 0;
    }

    // -------- epilogue --------
    const float* bv = bias + (size_t)e * LDB;
    const float bscale = (ks == 0) ? 1.0f : 0.0f;   // bias once per K-split group
#pragma unroll
    for (int mf = 0; mf < 4; ++mf) {
        int rl = wm + mf * 16 + g;
#pragma unroll
        for (int nf = 0; nf < 4; ++nf) {
            int col = n0 + wn + nf * 8 + 2 * t;
            float bb0 = bv[col] * bscale, bb1 = bv[col + 1] * bscale;
#pragma unroll
            for (int half = 0; half < 2; ++half) {
                int mrow = m0 + rl + half * 8;
                if (mrow >= cnt) continue;
                float v0 = acc[mf][nf][half * 2 + 0] + bb0;
                float v1 = acc[mf][nf][half * 2 + 1] + bb1;
                if (PHASE == 1) {
                    size_t o = (size_t)(base + mrow) * FDIM + col;
                    g_hmid[o]     = f2tf(gelu_exact(v0));
                    g_hmid[o + 1] = f2tf(gelu_exact(v1));
                } else {
                    int slot = base + mrow;
                    int tok = g_slot_tok[slot];
                    float w = g_slot_w[slot];
                    atomicAdd(&out[(size_t)tok * HDIM + col],     w * v0);
                    atomicAdd(&out[(size_t)tok * HDIM + col + 1], w * v1);
                }
            }
        }
    }
}

// ---------------- launch ----------------
extern "C" void kernel_launch(void* const* d_in, const int* in_sizes, int n_in,
                              void* d_out, int out_size) {
    const float* x  = (const float*)d_in[0];
    const float* gw = (const float*)d_in[1];
    const float* gb = (const float*)d_in[2];
    const float* w1 = (const float*)d_in[3];
    const float* b1 = (const float*)d_in[4];
    const float* w2 = (const float*)d_in[5];
    const float* b2 = (const float*)d_in[6];
    float* out = (float*)d_out;

    cudaFuncSetAttribute(moe_gemm<1, 1>, cudaFuncAttributeMaxDynamicSharedMemorySize, SMEM_REQ);
    cudaFuncSetAttribute(moe_gemm<2, 4>, cudaFuncAttributeMaxDynamicSharedMemorySize, SMEM_REQ);

    zero_kernel<<<(NTOK * HDIM + 255) / 256, 256>>>(out);
    gate_kernel<<<NTOK / 8, 256>>>(x, gw, gb);
    scan_kernel<<<1, 32>>>();
    scatter_kernel<<<(NTOK + 255) / 256, 256>>>();

    round_x_k<<<(NTOK * HDIM + 255) / 256, 256>>>(x);
    round_w1_k<<<(ENUM * HDIM * FDIM + 255) / 256, 256>>>(w1);
    round_w2_k<<<(ENUM * FDIM * HDIM + 255) / 256, 256>>>(w2);

    moe_gemm<1, 1><<<dim3(FDIM / 128, NSLOT / 128, ENUM), 256, SMEM_REQ>>>(b1, nullptr);
    moe_gemm<2, 4><<<dim3(HDIM / 128, NSLOT / 128, ENUM * 4), 256, SMEM_REQ>>>(b2, out);
}

// round 8
// speedup vs baseline: 1.6182x; 1.3691x over previous
#include <cuda_runtime.h>
#include <cuda_fp16.h>
#include <cstdint>
#include <math.h>

#define NTOK 4096
#define HDIM 768
#define FDIM 3072
#define ENUM 6
#define NSLOT (NTOK * 2)

// fp16 tiles: A 128x32 halfs, B 128x32 halfs, row pitch 40 halfs (80B, 16B-aligned)
#define ROWP 40
#define TILE_H (128 * ROWP)          // halfs per tile
#define STG_H  (2 * TILE_H)          // A + B
#define N_ST 4
#define SMEM_REQ (N_ST * STG_H * 2)  // 81920 B -> 2 CTAs/SM (164KB)

// ---------------- device scratch (no allocations allowed) ----------------
__device__ int    g_counts[ENUM];
__device__ int    g_offsets[ENUM + 1];
__device__ int    g_fill[ENUM];
__device__ int    g_tk_idx[NSLOT];
__device__ float  g_tk_w[NSLOT];
__device__ int    g_slot_tok[NSLOT];
__device__ float  g_slot_w[NSLOT];
__device__ __half g_xh[(size_t)NTOK * HDIM];           // fp16 x
__device__ __half g_hmidh[(size_t)NSLOT * FDIM];       // fp16 mid acts
__device__ __half g_w1h[(size_t)ENUM * FDIM * HDIM];   // w1^T fp16 [E][F][H] = [N][K]
__device__ __half g_w2h[(size_t)ENUM * HDIM * FDIM];   // w2^T fp16 [E][H][F] = [N][K]

// ---------------- helpers ----------------
__device__ __forceinline__ float gelu_exact(float x) {
    return 0.5f * x * (1.0f + erff(x * 0.7071067811865476f));
}
__device__ __forceinline__ uint32_t smem_u32(const void* p) {
    uint32_t a;
    asm("{ .reg .u64 t; cvta.to.shared.u64 t, %1; cvt.u32.u64 %0, t; }" : "=r"(a) : "l"(p));
    return a;
}
__device__ __forceinline__ void cp16(uint32_t dst, const void* src, bool pred) {
    int sz = pred ? 16 : 0;   // src-size 0 => zero-fill
    asm volatile("cp.async.cg.shared.global [%0], [%1], 16, %2;"
                 :: "r"(dst), "l"(src), "r"(sz) : "memory");
}
#define CP_COMMIT() asm volatile("cp.async.commit_group;" ::: "memory")
#define CP_WAIT(n)  asm volatile("cp.async.wait_group %0;" :: "n"(n) : "memory")

__device__ __forceinline__ void mma_f16(float* c, const uint32_t* a, const uint32_t* b) {
    asm volatile(
        "mma.sync.aligned.m16n8k16.row.col.f32.f16.f16.f32 "
        "{%0,%1,%2,%3}, {%4,%5,%6,%7}, {%8,%9}, {%0,%1,%2,%3};\n"
        : "+f"(c[0]), "+f"(c[1]), "+f"(c[2]), "+f"(c[3])
        : "r"(a[0]), "r"(a[1]), "r"(a[2]), "r"(a[3]), "r"(b[0]), "r"(b[1]));
}

// ---------------- kernel: zero output + routing counters ----------------
__global__ void zero_kernel(float* __restrict__ out) {
    int i = blockIdx.x * blockDim.x + threadIdx.x;
    if (i < NTOK * HDIM) out[i] = 0.0f;
    if (i < ENUM) { g_counts[i] = 0; g_fill[i] = 0; }
}

// ---------------- fp16 conversion into DEVICE-SYMBOL scratch ----------------
// (destinations referenced from device code; host-passed __device__ symbols
//  silently hit the host shadow via ATS on GB300 — the R3/R4 bug)
__global__ void conv_x_k(const float* __restrict__ src) {
    int i = blockIdx.x * blockDim.x + threadIdx.x;
    if (i < NTOK * HDIM) g_xh[i] = __float2half_rn(src[i]);
}
// w1 [E][H][F] -> g_w1h [E][F][H]
__global__ void prep_w1_k(const float* __restrict__ src) {
    __shared__ float t[32][33];
    const int e = blockIdx.z;
    const int c0 = blockIdx.x * 32, r0 = blockIdx.y * 32;   // c: F dim, r: H dim
    const int tx = threadIdx.x & 31, ty = threadIdx.x >> 5;
    const float* s = src + (size_t)e * HDIM * FDIM;
    __half* d = g_w1h + (size_t)e * FDIM * HDIM;
#pragma unroll
    for (int i = 0; i < 32; i += 8)
        t[ty + i][tx] = s[(size_t)(r0 + ty + i) * FDIM + c0 + tx];
    __syncthreads();
#pragma unroll
    for (int i = 0; i < 32; i += 8)
        d[(size_t)(c0 + ty + i) * HDIM + r0 + tx] = __float2half_rn(t[tx][ty + i]);
}
// w2 [E][F][H] -> g_w2h [E][H][F]
__global__ void prep_w2_k(const float* __restrict__ src) {
    __shared__ float t[32][33];
    const int e = blockIdx.z;
    const int c0 = blockIdx.x * 32, r0 = blockIdx.y * 32;   // c: H dim, r: F dim
    const int tx = threadIdx.x & 31, ty = threadIdx.x >> 5;
    const float* s = src + (size_t)e * FDIM * HDIM;
    __half* d = g_w2h + (size_t)e * HDIM * FDIM;
#pragma unroll
    for (int i = 0; i < 32; i += 8)
        t[ty + i][tx] = s[(size_t)(r0 + ty + i) * HDIM + c0 + tx];
    __syncthreads();
#pragma unroll
    for (int i = 0; i < 32; i += 8)
        d[(size_t)(c0 + ty + i) * FDIM + r0 + tx] = __float2half_rn(t[tx][ty + i]);
}

// ---------------- gate: scores + top-2 + softmax + counts ----------------
__global__ void gate_kernel(const float* __restrict__ x,
                            const float* __restrict__ gw,
                            const float* __restrict__ gb) {
    const int warp = threadIdx.x >> 5;
    const int lane = threadIdx.x & 31;
    const int tok = blockIdx.x * 8 + warp;
    if (tok >= NTOK) return;

    float acc[ENUM];
#pragma unroll
    for (int e = 0; e < ENUM; ++e) acc[e] = 0.0f;

    const float* xr = x + (size_t)tok * HDIM;
    for (int h = lane; h < HDIM; h += 32) {
        float xv = xr[h];
#pragma unroll
        for (int e = 0; e < ENUM; ++e) acc[e] += xv * gw[h * ENUM + e];
    }
#pragma unroll
    for (int e = 0; e < ENUM; ++e) {
#pragma unroll
        for (int off = 16; off > 0; off >>= 1)
            acc[e] += __shfl_xor_sync(0xffffffffu, acc[e], off);
    }
    if (lane == 0) {
        float best = -1e30f, sec = -1e30f;
        int bi = 0, si = 0;
#pragma unroll
        for (int e = 0; e < ENUM; ++e) {
            float s = acc[e] + gb[e];
            if (s > best) { sec = best; si = bi; best = s; bi = e; }
            else if (s > sec) { sec = s; si = e; }
        }
        float r = expf(sec - best);
        float inv = 1.0f / (1.0f + r);
        g_tk_idx[tok * 2]     = bi;
        g_tk_idx[tok * 2 + 1] = si;
        g_tk_w[tok * 2]       = inv;
        g_tk_w[tok * 2 + 1]   = r * inv;
        atomicAdd(&g_counts[bi], 1);
        atomicAdd(&g_counts[si], 1);
    }
}

__global__ void scan_kernel() {
    if (threadIdx.x == 0 && blockIdx.x == 0) {
        int o = 0;
#pragma unroll
        for (int e = 0; e < ENUM; ++e) { g_offsets[e] = o; o += g_counts[e]; }
        g_offsets[ENUM] = o;
    }
}

__global__ void scatter_kernel() {
    int n = blockIdx.x * blockDim.x + threadIdx.x;
    if (n >= NTOK) return;
#pragma unroll
    for (int k = 0; k < 2; ++k) {
        int e = g_tk_idx[n * 2 + k];
        int pos = g_offsets[e] + atomicAdd(&g_fill[e], 1);
        g_slot_tok[pos] = n;
        g_slot_w[pos]   = g_tk_w[n * 2 + k];
    }
}

// ---------------- grouped GEMM (fp16 mma m16n8k16), 4-stage cp.async ----------
// Both A and B live as [row][K] fp16 (B = pre-transposed weights), K-contiguous.
// PHASE 1 (KSPLIT=1): hmidh = half(gelu(gather(xh) @ w1h^T + b1))
// PHASE 2 (KSPLIT=4): out += slot_w * (hmidh @ w2h^T [+ b2 if ks==0]) via atomicAdd
template <int PHASE, int KSPLIT>
__global__ void __launch_bounds__(256, 2) moe_gemm(const float* __restrict__ bias,
                                                   float* __restrict__ out) {
    constexpr int KTOT = (PHASE == 1) ? HDIM : FDIM;
    constexpr int KDIM = KTOT / KSPLIT;
    constexpr int NN   = (PHASE == 1) ? FDIM : HDIM;
    constexpr int KT   = KDIM / 32;

    const int e    = blockIdx.z / KSPLIT;
    const int ks   = blockIdx.z % KSPLIT;
    const int kb   = ks * KDIM;
    const int base = g_offsets[e];
    const int cnt  = g_offsets[e + 1] - base;
    const int m0   = blockIdx.y * 128;
    if (m0 >= cnt) return;
    const int n0 = blockIdx.x * 128;

    const __half* Wh = ((PHASE == 1) ? g_w1h : g_w2h) + (size_t)e * (size_t)NN * KTOT;

    extern __shared__ __half Sh[];   // [N_ST][A 128*ROWP | B 128*ROWP]
    const uint32_t sb = smem_u32(Sh);

    const int tid = threadIdx.x, wid = tid >> 5, lane = tid & 31;

    // cp.async mapping: thread -> (row = tid>>1, 32B half-row chunk = tid&1)
    const int crow = tid >> 1;
    const int coff = (tid & 1) * 16;      // halfs offset within row

    const __half* aptr;                    // A row source (gathered / contiguous)
    {
        int m = m0 + crow;
        if (m < cnt) {
            if (PHASE == 1) aptr = g_xh + (size_t)g_slot_tok[base + m] * HDIM + kb + coff;
            else            aptr = g_hmidh + (size_t)(base + m) * FDIM + kb + coff;
        } else aptr = nullptr;
    }
    const __half* bptr = Wh + (size_t)(n0 + crow) * KTOT + kb + coff;
    const uint32_t sdst = (uint32_t)(crow * ROWP + coff) * 2;   // bytes within tile

    auto issue = [&](int b, int k0) {   // k0 in halfs
        uint32_t a_s = sb + (uint32_t)b * STG_H * 2 + sdst;
        uint32_t b_s = a_s + TILE_H * 2;
        cp16(a_s,      aptr ? (aptr + k0)     : (const __half*)Wh, aptr != nullptr);
        cp16(a_s + 16, aptr ? (aptr + k0 + 8) : (const __half*)Wh, aptr != nullptr);
        cp16(b_s,      bptr + k0, true);
        cp16(b_s + 16, bptr + k0 + 8, true);
    };

    issue(0, 0);  CP_COMMIT();
    issue(1, 32); CP_COMMIT();
    issue(2, 64); CP_COMMIT();

    const int wm = (wid >> 2) * 64;
    const int wn = (wid & 3) * 32;
    const int g = lane >> 2, t = lane & 3;

    float acc[4][4][4];
#pragma unroll
    for (int mf = 0; mf < 4; ++mf)
#pragma unroll
        for (int nf = 0; nf < 4; ++nf)
#pragma unroll
            for (int c = 0; c < 4; ++c) acc[mf][nf][c] = 0.0f;

    int st = 0;
    for (int kt = 0; kt < KT; ++kt) {
        CP_WAIT(2);                   // oldest outstanding group (stage st) landed
        __syncthreads();              // + all warps done with tile kt-1 (stage st-1)
        if (kt + 3 < KT) {
            int s3 = st + 3; if (s3 >= N_ST) s3 -= N_ST;
            issue(s3, (kt + 3) * 32); // overwrites stage consumed at iter kt-1: safe
            CP_COMMIT();
        }

        const __half* au = Sh + st * STG_H;
        const __half* bu = au + TILE_H;
#pragma unroll
        for (int s = 0; s < 2; ++s) {   // two k16 steps per 32-half tile
            uint32_t af[4][4];
#pragma unroll
            for (int mf = 0; mf < 4; ++mf) {
                const __half* Ap = au + (wm + mf * 16 + g) * ROWP + s * 16 + 2 * t;
                af[mf][0] = *(const uint32_t*)(Ap);
                af[mf][1] = *(const uint32_t*)(Ap + 8 * ROWP);
                af[mf][2] = *(const uint32_t*)(Ap + 8);
                af[mf][3] = *(const uint32_t*)(Ap + 8 * ROWP + 8);
            }
            uint32_t bf[4][2];
#pragma unroll
            for (int nf = 0; nf < 4; ++nf) {
                const __half* Bp = bu + (wn + nf * 8 + g) * ROWP + s * 16 + 2 * t;
                bf[nf][0] = *(const uint32_t*)(Bp);
                bf[nf][1] = *(const uint32_t*)(Bp + 8);
            }
#pragma unroll
            for (int mf = 0; mf < 4; ++mf)
#pragma unroll
                for (int nf = 0; nf < 4; ++nf)
                    mma_f16(acc[mf][nf], af[mf], bf[nf]);
        }
        if (++st == N_ST) st = 0;
    }

    // -------- epilogue --------
    const float* bv = bias + (size_t)e * NN;
    const float bscale = (ks == 0) ? 1.0f : 0.0f;   // bias once per K-split group
#pragma unroll
    for (int mf = 0; mf < 4; ++mf) {
        int rl = wm + mf * 16 + g;
#pragma unroll
        for (int nf = 0; nf < 4; ++nf) {
            int col = n0 + wn + nf * 8 + 2 * t;
            float bb0 = bv[col] * bscale, bb1 = bv[col + 1] * bscale;
#pragma unroll
            for (int half = 0; half < 2; ++half) {
                int mrow = m0 + rl + half * 8;
                if (mrow >= cnt) continue;
                float v0 = acc[mf][nf][half * 2 + 0] + bb0;
                float v1 = acc[mf][nf][half * 2 + 1] + bb1;
                if (PHASE == 1) {
                    size_t o = (size_t)(base + mrow) * FDIM + col;
                    *(__half2*)&g_hmidh[o] =
                        __float22half2_rn(make_float2(gelu_exact(v0), gelu_exact(v1)));
                } else {
                    int slot = base + mrow;
                    int tok = g_slot_tok[slot];
                    float w = g_slot_w[slot];
                    atomicAdd(&out[(size_t)tok * HDIM + col],     w * v0);
                    atomicAdd(&out[(size_t)tok * HDIM + col + 1], w * v1);
                }
            }
        }
    }
}

// ---------------- launch ----------------
extern "C" void kernel_launch(void* const* d_in, const int* in_sizes, int n_in,
                              void* d_out, int out_size) {
    const float* x  = (const float*)d_in[0];
    const float* gw = (const float*)d_in[1];
    const float* gb = (const float*)d_in[2];
    const float* w1 = (const float*)d_in[3];
    const float* b1 = (const float*)d_in[4];
    const float* w2 = (const float*)d_in[5];
    const float* b2 = (const float*)d_in[6];
    float* out = (float*)d_out;

    cudaFuncSetAttribute(moe_gemm<1, 1>, cudaFuncAttributeMaxDynamicSharedMemorySize, SMEM_REQ);
    cudaFuncSetAttribute(moe_gemm<2, 4>, cudaFuncAttributeMaxDynamicSharedMemorySize, SMEM_REQ);

    zero_kernel<<<(NTOK * HDIM + 255) / 256, 256>>>(out);
    gate_kernel<<<NTOK / 8, 256>>>(x, gw, gb);
    scan_kernel<<<1, 32>>>();
    scatter_kernel<<<(NTOK + 255) / 256, 256>>>();

    conv_x_k<<<(NTOK * HDIM + 255) / 256, 256>>>(x);
    prep_w1_k<<<dim3(FDIM / 32, HDIM / 32, ENUM), 256>>>(w1);
    prep_w2_k<<<dim3(HDIM / 32, FDIM / 32, ENUM), 256>>>(w2);

    moe_gemm<1, 1><<<dim3(FDIM / 128, NSLOT / 128, ENUM), 256, SMEM_REQ>>>(b1, nullptr);
    moe_gemm<2, 4><<<dim3(HDIM / 128, NSLOT / 128, ENUM * 4), 256, SMEM_REQ>>>(b2, out);
}